// round 2
// baseline (speedup 1.0000x reference)
#include <cuda_runtime.h>
#include <cstdint>

// tcgen05 is arch-SPECIFIC: only legal when compiling for sm_103a/sm_100a/sm_101a.
// The harness also runs a plain compute_103->sm_103 pass, which must not see tcgen05.
#if !defined(__CUDA_ARCH__) || defined(__CUDA_ARCH_FEAT_SM103_ALL) || \
    defined(__CUDA_ARCH_FEAT_SM100_ALL) || defined(__CUDA_ARCH_FEAT_SM101_ALL)
#define HAS_TC 1
#else
#define HAS_TC 0
#endif

// ---------------- problem constants ----------------
#define IN_F   2048
#define OUT_F  2048
#define MT     128      // CTA M tile (nodes)
#define NT     128      // CTA N tile (outputs)
#define KT     32       // K tile per stage (32 tf32 = 128B row, SW128 atom width)
#define K_PER_MMA 8     // tf32: 32B / 4B
#define NKSTEP (KT / K_PER_MMA)   // 4 MMA dispatches per k-tile

// smem layout (dynamic):
//  [0:8)    tmem ptr
//  [8:16)   mbar0
//  [16:24)  mbar1
//  [1024 .. ) stage0: A (16KB) + B (16KB); stage1 same
#define SM_TMEM  0
#define SM_BAR0  8
#define SM_BAR1  16
#define SM_BUF   1024
#define STAGE_BYTES (MT*KT*4 + NT*KT*4)   // 32768
#define SMEM_TOTAL  (SM_BUF + 2*STAGE_BYTES)

// dense weight scratch
__device__ float g_W[OUT_F * IN_F];

// ---------------- PTX helpers ----------------
__device__ __forceinline__ uint32_t smem_u32(const void* p) {
    uint32_t a;
    asm("{ .reg .u64 t; cvta.to.shared.u64 t, %1; cvt.u32.u64 %0, t; }" : "=r"(a) : "l"(p));
    return a;
}
__device__ __forceinline__ uint32_t swz(uint32_t off) { return off ^ ((off >> 3) & 0x70); }

// fp32 -> tf32 round-to-nearest (kills truncation bias of raw SS operands)
__device__ __forceinline__ uint32_t f2tf(float f) {
    uint32_t r; asm("cvt.rna.tf32.f32 %0, %1;" : "=r"(r) : "f"(f)); return r;
}

#if HAS_TC
__device__ __forceinline__ uint32_t elect_one() {
    uint32_t p;
    asm volatile("{ .reg .pred p; elect.sync _|p, 0xFFFFFFFF; selp.b32 %0, 1, 0, p; }" : "=r"(p));
    return p;
}
#define MBAR_INIT(addr, cnt) \
    asm volatile("mbarrier.init.shared.b64 [%0], %1;" :: "r"(addr), "r"(cnt) : "memory")
#define TC_ALLOC(dst, n) \
    asm volatile("tcgen05.alloc.cta_group::1.sync.aligned.shared::cta.b32 [%0], %1;" :: "r"(dst), "r"(n) : "memory")
#define TC_DEALLOC(t, n) \
    asm volatile("tcgen05.dealloc.cta_group::1.sync.aligned.b32 %0, %1;" :: "r"(t), "r"(n))
#define TC_RELINQ() \
    asm volatile("tcgen05.relinquish_alloc_permit.cta_group::1.sync.aligned;")
#define TC_COMMIT(mbar) \
    asm volatile("tcgen05.commit.cta_group::1.mbarrier::arrive::one.shared::cluster.b64 [%0];" :: "r"(mbar) : "memory")
#define TC_FENCE_AFTER()  asm volatile("tcgen05.fence::after_thread_sync;" ::: "memory")
#define TC_FENCE_BEFORE() asm volatile("tcgen05.fence::before_thread_sync;" ::: "memory")
#define TC_WAIT_LD()      asm volatile("tcgen05.wait::ld.sync.aligned;" ::: "memory")
#define FENCE_ASYNC_SHARED() asm volatile("fence.proxy.async.shared::cta;" ::: "memory")

#define MBAR_WAIT(mbar, parity) do {                                          \
    uint32_t _m = (mbar); uint32_t _p = (parity); uint32_t _d;                \
    asm volatile("{ .reg .pred p; mbarrier.try_wait.parity.acquire.cta.shared::cta.b64 p, [%1], %2; selp.b32 %0,1,0,p; }" \
        : "=r"(_d) : "r"(_m), "r"(_p) : "memory");                            \
    if (!_d) {                                                                \
        asm volatile("{ .reg .pred P; L%=: mbarrier.try_wait.parity.acquire.cta.shared::cta.b64 P, [%0], %1, 0x989680; @P bra.uni D%=; bra.uni L%=; D%=: }" \
            :: "r"(_m), "r"(_p) : "memory");                                  \
    }                                                                         \
} while (0)

#define TC_LD_32X32B_X32(r, t)                                                \
    asm volatile("tcgen05.ld.sync.aligned.32x32b.x32.b32 "                    \
        "{%0,%1,%2,%3,%4,%5,%6,%7,%8,%9,%10,%11,%12,%13,%14,%15,"             \
        "%16,%17,%18,%19,%20,%21,%22,%23,%24,%25,%26,%27,%28,%29,%30,%31}, [%32];" \
        : "=r"((r)[0]),"=r"((r)[1]),"=r"((r)[2]),"=r"((r)[3]),                \
          "=r"((r)[4]),"=r"((r)[5]),"=r"((r)[6]),"=r"((r)[7]),                \
          "=r"((r)[8]),"=r"((r)[9]),"=r"((r)[10]),"=r"((r)[11]),              \
          "=r"((r)[12]),"=r"((r)[13]),"=r"((r)[14]),"=r"((r)[15]),            \
          "=r"((r)[16]),"=r"((r)[17]),"=r"((r)[18]),"=r"((r)[19]),            \
          "=r"((r)[20]),"=r"((r)[21]),"=r"((r)[22]),"=r"((r)[23]),            \
          "=r"((r)[24]),"=r"((r)[25]),"=r"((r)[26]),"=r"((r)[27]),            \
          "=r"((r)[28]),"=r"((r)[29]),"=r"((r)[30]),"=r"((r)[31])             \
        : "r"(t))

// SW128 K-major descriptor: LBO=1, SBO=64, layout=SW128, Blackwell version=1
__device__ __forceinline__ uint64_t make_desc(uint32_t addr) {
    const uint64_t base = (uint64_t(2) << 61) | (uint64_t(1) << 46)
                        | (uint64_t(64) << 32) | (uint64_t(1) << 16);
    return base | ((uint64_t)(addr >> 4) & 0x3FFF);
}

// SS tf32 MMA, cta_group::1
__device__ __forceinline__ void mma_tf32_ss(uint32_t d, uint64_t ad, uint64_t bd,
                                            uint32_t idesc, uint32_t acc) {
    asm volatile(
        "{ .reg .pred p; setp.ne.u32 p, %5, 0;\n\t"
        "tcgen05.mma.cta_group::1.kind::tf32 [%0], %1, %2, %3, {%4,%4,%4,%4}, p; }"
        :: "r"(d), "l"(ad), "l"(bd), "r"(idesc), "r"(0u), "r"(acc) : "memory");
}
#endif  // HAS_TC

// ---------------- kernels ----------------
__global__ void zero_w_kernel() {
    int i = blockIdx.x * blockDim.x + threadIdx.x;
    int n = OUT_F * IN_F;
    for (; i < n; i += gridDim.x * blockDim.x) g_W[i] = 0.0f;
}

__global__ void scatter_kernel(const float* __restrict__ vals,
                               const int* __restrict__ rows,
                               const int* __restrict__ cols, int nnz) {
    int i = blockIdx.x * blockDim.x + threadIdx.x;
    if (i < nnz) atomicAdd(&g_W[rows[i] * IN_F + cols[i]], vals[i]);
}

#if HAS_TC
__device__ __forceinline__ void load_tile(const float* __restrict__ src_base,
                                          char* smem, uint32_t buf_off, int tid) {
    // 128 rows x 32 tf32 (128B/row), 16B chunks, SW128-swizzled stores
#pragma unroll
    for (int j = tid; j < MT * 8; j += 128) {
        int r = j >> 3, c4 = j & 7;
        float4 v = *(const float4*)(src_base + (size_t)r * IN_F + c4 * 4);
        uint4 t;
        t.x = f2tf(v.x); t.y = f2tf(v.y); t.z = f2tf(v.z); t.w = f2tf(v.w);
        uint32_t off = (uint32_t)(r * (KT * 4) + c4 * 16);
        *(uint4*)(smem + buf_off + swz(off)) = t;
    }
}
#endif

__global__ void __launch_bounds__(128, 1)
gemm_tf32_kernel(const float* __restrict__ x,
                 const float* __restrict__ bias,
                 float* __restrict__ y, int k_total) {
    extern __shared__ char smem[];
    const int tid = threadIdx.x;
    const int m_base = blockIdx.x * MT;
    const int n_base = blockIdx.y * NT;

#if HAS_TC
    const uint32_t sb = smem_u32(smem);
    const int wid = tid >> 5, lid = tid & 31;
    const int NK = k_total / KT;

    if (tid == 0) { MBAR_INIT(sb + SM_BAR0, 1); MBAR_INIT(sb + SM_BAR1, 1); }
    if (wid == 0) { TC_ALLOC(sb + SM_TMEM, 128); TC_RELINQ(); }
    __syncthreads();
    uint32_t tmem;
    asm volatile("ld.shared.b32 %0, [%1];" : "=r"(tmem) : "r"(sb + SM_TMEM));

    const float* xA = x + (size_t)m_base * IN_F;
    const float* wB = g_W + (size_t)n_base * IN_F;

    // prologue: tiles 0 and 1
    load_tile(xA + 0 * KT, smem, SM_BUF, tid);
    load_tile(wB + 0 * KT, smem, SM_BUF + MT * KT * 4, tid);
    load_tile(xA + 1 * KT, smem, SM_BUF + STAGE_BYTES, tid);
    load_tile(wB + 1 * KT, smem, SM_BUF + STAGE_BYTES + MT * KT * 4, tid);
    FENCE_ASYNC_SHARED();
    __syncthreads();

    const uint32_t IDESC = (1u << 4) | (2u << 7) | (2u << 10)
                         | ((NT / 8) << 17) | ((MT / 16) << 24);

    for (int i = 0; i < NK; ++i) {
        const int b = i & 1;
        const uint32_t aoff = SM_BUF + (uint32_t)b * STAGE_BYTES;
        const uint32_t boff = aoff + MT * KT * 4;
        const uint32_t bar = sb + (b ? SM_BAR1 : SM_BAR0);

        if (wid == 0) {
            if (elect_one()) {
                uint64_t ad = make_desc(sb + aoff);
                uint64_t bd = make_desc(sb + boff);
#pragma unroll
                for (int s = 0; s < NKSTEP; ++s)
                    mma_tf32_ss(tmem, ad + s * 2, bd + s * 2, IDESC,
                                (i == 0 && s == 0) ? 0u : 1u);
                TC_COMMIT(bar);
            }
        }
        // all threads wait until MMA for tile i has drained (frees buffer b)
        MBAR_WAIT(bar, (uint32_t)((i >> 1) & 1));

        if (i + 2 < NK) {
            load_tile(xA + (size_t)(i + 2) * KT, smem, aoff, tid);
            load_tile(wB + (size_t)(i + 2) * KT, smem, boff, tid);
            FENCE_ASYNC_SHARED();
        }
        __syncthreads();
    }

    // epilogue: D [128x128] f32 in TMEM, add bias, store
    TC_FENCE_AFTER();
    const size_t row = (size_t)(m_base + wid * 32 + lid);
#pragma unroll
    for (int c0 = 0; c0 < NT; c0 += 32) {
        uint32_t r[32];
        TC_LD_32X32B_X32(r, tmem + c0);
        TC_WAIT_LD();
        float* dst = y + row * OUT_F + n_base + c0;
#pragma unroll
        for (int c = 0; c < 32; c += 4) {
            float4 o;
            o.x = __uint_as_float(r[c + 0]) + __ldg(bias + n_base + c0 + c + 0);
            o.y = __uint_as_float(r[c + 1]) + __ldg(bias + n_base + c0 + c + 1);
            o.z = __uint_as_float(r[c + 2]) + __ldg(bias + n_base + c0 + c + 2);
            o.w = __uint_as_float(r[c + 3]) + __ldg(bias + n_base + c0 + c + 3);
            *(float4*)(dst + c) = o;
        }
    }
    TC_FENCE_BEFORE();
    __syncthreads();
    if (wid == 0) TC_DEALLOC(tmem, 128);

#else  // ---------------- non-sm_103a fallback (compiles for plain sm_103) ----
    // Correct (slow) smem-tiled fp32 GEMM. Only used if the driver ever picks
    // the non-'a' cubin — on GB300 the sm_103a cubin is an exact match.
    float* wsm = (float*)smem;          // [32][33] W tile
    const int m = m_base + tid;         // this thread's row
    const float* xrow = x + (size_t)m * IN_F;

    for (int nb = 0; nb < NT; nb += 32) {
        float acc[32];
#pragma unroll
        for (int j = 0; j < 32; ++j) acc[j] = 0.0f;

        for (int k0 = 0; k0 < k_total; k0 += 32) {
            // cooperative load of W[n_base+nb .. +32)[k0 .. k0+32) into smem
            for (int e = tid; e < 32 * 32; e += 128) {
                int j = e >> 5, kk = e & 31;
                wsm[j * 33 + kk] = g_W[(size_t)(n_base + nb + j) * IN_F + k0 + kk];
            }
            __syncthreads();
#pragma unroll 8
            for (int kk = 0; kk < 32; ++kk) {
                float xv = __ldg(xrow + k0 + kk);
#pragma unroll
                for (int j = 0; j < 32; ++j)
                    acc[j] += xv * wsm[j * 33 + kk];
            }
            __syncthreads();
        }
        float* dst = y + (size_t)m * OUT_F + n_base + nb;
#pragma unroll
        for (int j = 0; j < 32; ++j)
            dst[j] = acc[j] + __ldg(bias + n_base + nb + j);
    }
#endif
}

// ---------------- launch ----------------
extern "C" void kernel_launch(void* const* d_in, const int* in_sizes, int n_in,
                              void* d_out, int out_size) {
    const float* x    = (const float*)d_in[0];
    const float* vals = (const float*)d_in[1];
    const float* bias = (const float*)d_in[2];
    const int*   rows = (const int*)d_in[3];
    const int*   cols = (const int*)d_in[4];
    float* y = (float*)d_out;

    const int nnz     = in_sizes[1];
    const int n_nodes = in_sizes[0] / IN_F;

    zero_w_kernel<<<1024, 1024>>>();
    scatter_kernel<<<(nnz + 255) / 256, 256>>>(vals, rows, cols, nnz);

    cudaFuncSetAttribute(gemm_tf32_kernel,
                         cudaFuncAttributeMaxDynamicSharedMemorySize, SMEM_TOTAL);
    dim3 grid(n_nodes / MT, OUT_F / NT);
    gemm_tf32_kernel<<<grid, 128, SMEM_TOTAL>>>(x, bias, y, IN_F);
}

// round 4
// speedup vs baseline: 1.8535x; 1.8535x over previous
#include <cuda_runtime.h>
#include <cstdint>

// tcgen05 is arch-SPECIFIC: only legal for sm_103a/sm_100a/sm_101a.
// The harness also runs a plain compute_103->sm_103 pass, which must not see tcgen05.
#if !defined(__CUDA_ARCH__) || defined(__CUDA_ARCH_FEAT_SM103_ALL) || \
    defined(__CUDA_ARCH_FEAT_SM100_ALL) || defined(__CUDA_ARCH_FEAT_SM101_ALL)
#define HAS_TC 1
#else
#define HAS_TC 0
#endif

// ---------------- problem constants ----------------
#define IN_F   2048
#define OUT_F  2048
#define MT     256      // CTA M tile (two 128-row MMA halves)
#define NT     256      // CTA N tile (one N=256 MMA)
#define KT     32       // K tile per stage (32 tf32 = 128B row = SW128 atom)
#define NKSTEP 4        // 4 tf32 K=8 dispatches per k-tile
#define NSTAGE 3
#define NTHREADS 256

// smem: [0:8) tmem ptr | [8,16,24) mbar0..2 | [1024..) 3 stages of 64KB
#define SM_TMEM  0
#define SM_BAR   8
#define SM_BUF   1024
#define A_BYTES  (MT*KT*4)            // 32768
#define B_BYTES  (NT*KT*4)            // 32768
#define STAGE_BYTES (A_BYTES + B_BYTES)   // 65536
#define SMEM_TOTAL  (SM_BUF + NSTAGE*STAGE_BYTES)   // 197632

// dense weight scratch
__device__ float g_W[OUT_F * IN_F];

// ---------------- helpers ----------------
__device__ __forceinline__ uint32_t smem_u32(const void* p) {
    uint32_t a;
    asm("{ .reg .u64 t; cvta.to.shared.u64 t, %1; cvt.u32.u64 %0, t; }" : "=r"(a) : "l"(p));
    return a;
}
__device__ __forceinline__ uint32_t swz(uint32_t off) { return off ^ ((off >> 3) & 0x70); }
__device__ __forceinline__ uint32_t f2tf(float f) {
    uint32_t r; asm("cvt.rna.tf32.f32 %0, %1;" : "=r"(r) : "f"(f)); return r;
}

#if HAS_TC
__device__ __forceinline__ uint32_t elect_one() {
    uint32_t p;
    asm volatile("{ .reg .pred p; elect.sync _|p, 0xFFFFFFFF; selp.b32 %0, 1, 0, p; }" : "=r"(p));
    return p;
}
#define MBAR_INIT(addr, cnt) \
    asm volatile("mbarrier.init.shared.b64 [%0], %1;" :: "r"(addr), "r"(cnt) : "memory")
#define TC_ALLOC(dst, n) \
    asm volatile("tcgen05.alloc.cta_group::1.sync.aligned.shared::cta.b32 [%0], %1;" :: "r"(dst), "r"(n) : "memory")
#define TC_DEALLOC(t, n) \
    asm volatile("tcgen05.dealloc.cta_group::1.sync.aligned.b32 %0, %1;" :: "r"(t), "r"(n))
#define TC_RELINQ() \
    asm volatile("tcgen05.relinquish_alloc_permit.cta_group::1.sync.aligned;")
#define TC_COMMIT(mbar) \
    asm volatile("tcgen05.commit.cta_group::1.mbarrier::arrive::one.shared::cluster.b64 [%0];" :: "r"(mbar) : "memory")
#define TC_FENCE_AFTER()  asm volatile("tcgen05.fence::after_thread_sync;" ::: "memory")
#define TC_FENCE_BEFORE() asm volatile("tcgen05.fence::before_thread_sync;" ::: "memory")
#define TC_WAIT_LD()      asm volatile("tcgen05.wait::ld.sync.aligned;" ::: "memory")
#define FENCE_ASYNC_SHARED() asm volatile("fence.proxy.async.shared::cta;" ::: "memory")

#define MBAR_WAIT(mbar, parity) do {                                          \
    uint32_t _m = (mbar); uint32_t _p = (parity); uint32_t _d;                \
    asm volatile("{ .reg .pred p; mbarrier.try_wait.parity.acquire.cta.shared::cta.b64 p, [%1], %2; selp.b32 %0,1,0,p; }" \
        : "=r"(_d) : "r"(_m), "r"(_p) : "memory");                            \
    if (!_d) {                                                                \
        asm volatile("{ .reg .pred P; L%=: mbarrier.try_wait.parity.acquire.cta.shared::cta.b64 P, [%0], %1, 0x989680; @P bra.uni D%=; bra.uni L%=; D%=: }" \
            :: "r"(_m), "r"(_p) : "memory");                                  \
    }                                                                         \
} while (0)

#define TC_LD_32X32B_X32(r, t)                                                \
    asm volatile("tcgen05.ld.sync.aligned.32x32b.x32.b32 "                    \
        "{%0,%1,%2,%3,%4,%5,%6,%7,%8,%9,%10,%11,%12,%13,%14,%15,"             \
        "%16,%17,%18,%19,%20,%21,%22,%23,%24,%25,%26,%27,%28,%29,%30,%31}, [%32];" \
        : "=r"((r)[0]),"=r"((r)[1]),"=r"((r)[2]),"=r"((r)[3]),                \
          "=r"((r)[4]),"=r"((r)[5]),"=r"((r)[6]),"=r"((r)[7]),                \
          "=r"((r)[8]),"=r"((r)[9]),"=r"((r)[10]),"=r"((r)[11]),              \
          "=r"((r)[12]),"=r"((r)[13]),"=r"((r)[14]),"=r"((r)[15]),            \
          "=r"((r)[16]),"=r"((r)[17]),"=r"((r)[18]),"=r"((r)[19]),            \
          "=r"((r)[20]),"=r"((r)[21]),"=r"((r)[22]),"=r"((r)[23]),            \
          "=r"((r)[24]),"=r"((r)[25]),"=r"((r)[26]),"=r"((r)[27]),            \
          "=r"((r)[28]),"=r"((r)[29]),"=r"((r)[30]),"=r"((r)[31])             \
        : "r"(t))

// SW128 K-major descriptor: LBO=1, SBO=64, Blackwell version=1
__device__ __forceinline__ uint64_t make_desc(uint32_t addr) {
    const uint64_t base = (uint64_t(2) << 61) | (uint64_t(1) << 46)
                        | (uint64_t(64) << 32) | (uint64_t(1) << 16);
    return base | ((uint64_t)(addr >> 4) & 0x3FFF);
}

__device__ __forceinline__ void mma_tf32_ss(uint32_t d, uint64_t ad, uint64_t bd,
                                            uint32_t idesc, uint32_t acc) {
    asm volatile(
        "{ .reg .pred p; setp.ne.u32 p, %5, 0;\n\t"
        "tcgen05.mma.cta_group::1.kind::tf32 [%0], %1, %2, %3, {%4,%4,%4,%4}, p; }"
        :: "r"(d), "l"(ad), "l"(bd), "r"(idesc), "r"(0u), "r"(acc) : "memory");
}
#endif  // HAS_TC

// ---------------- prologue kernels ----------------
__global__ void zero_w_kernel() {
    int i = blockIdx.x * blockDim.x + threadIdx.x;
    int n = OUT_F * IN_F;
    for (; i < n; i += gridDim.x * blockDim.x) g_W[i] = 0.0f;
}

__global__ void scatter_kernel(const float* __restrict__ vals,
                               const int* __restrict__ rows,
                               const int* __restrict__ cols, int nnz) {
    int i = blockIdx.x * blockDim.x + threadIdx.x;
    if (i < nnz) atomicAdd(&g_W[rows[i] * IN_F + cols[i]], vals[i]);
}

#if HAS_TC
// load a [256 rows x 32 tf32] tile (row stride IN_F) into SW128 smem
__device__ __forceinline__ void load_tile(const float* __restrict__ src,
                                          char* smem, uint32_t off, int tid) {
#pragma unroll
    for (int j = tid; j < 256 * 8; j += NTHREADS) {
        int r = j >> 3, c4 = j & 7;
        float4 v = *(const float4*)(src + (size_t)r * IN_F + c4 * 4);
        uint4 t;
        t.x = f2tf(v.x); t.y = f2tf(v.y); t.z = f2tf(v.z); t.w = f2tf(v.w);
        *(uint4*)(smem + off + swz((uint32_t)(r * 128 + c4 * 16))) = t;
    }
}
#endif

__global__ void __launch_bounds__(NTHREADS, 1)
gemm_tf32_kernel(const float* __restrict__ x,
                 const float* __restrict__ bias,
                 float* __restrict__ y, int k_total) {
    extern __shared__ char smem[];
    const int tid = threadIdx.x;
    const int n_base = blockIdx.x * NT;   // x-fastest: all n-tiles of one m-band concurrent
    const int m_base = blockIdx.y * MT;

#if HAS_TC
    const uint32_t sb = smem_u32(smem);
    const int wid = tid >> 5, lid = tid & 31;
    const int NK = k_total / KT;   // 64

    if (tid == 0) {
#pragma unroll
        for (int s = 0; s < NSTAGE; ++s) MBAR_INIT(sb + SM_BAR + 8 * s, 1);
    }
    if (wid == 0) { TC_ALLOC(sb + SM_TMEM, 512); TC_RELINQ(); }
    __syncthreads();
    uint32_t tmem;
    asm volatile("ld.shared.b32 %0, [%1];" : "=r"(tmem) : "r"(sb + SM_TMEM));

    const float* xA = x + (size_t)m_base * IN_F;
    const float* wB = g_W + (size_t)n_base * IN_F;

    const uint32_t IDESC = (1u << 4) | (2u << 7) | (2u << 10)
                         | ((NT / 8) << 17) | ((128 / 16) << 24);

    for (int i = 0; i < NK; ++i) {
        const int s = i % NSTAGE;
        const uint32_t soff = SM_BUF + (uint32_t)s * STAGE_BYTES;
        const uint32_t bar  = sb + SM_BAR + 8 * s;

        // free the stage: wait for MMA of tile i-NSTAGE (commit #(i/NSTAGE - 1))
        if (i >= NSTAGE) MBAR_WAIT(bar, (uint32_t)((i / NSTAGE - 1) & 1));

        load_tile(xA + (size_t)i * KT, smem, soff, tid);            // A: 256xKT
        load_tile(wB + (size_t)i * KT, smem, soff + A_BYTES, tid);  // B: 256xKT
        FENCE_ASYNC_SHARED();
        __syncthreads();

        if (wid == 0 && elect_one()) {
            uint64_t ad0 = make_desc(sb + soff);                 // A rows 0-127
            uint64_t ad1 = make_desc(sb + soff + A_BYTES / 2);   // A rows 128-255
            uint64_t bd  = make_desc(sb + soff + A_BYTES);
            uint32_t acc = (i == 0) ? 0u : 1u;
#pragma unroll
            for (int k = 0; k < NKSTEP; ++k) {
                mma_tf32_ss(tmem +   0, ad0 + k * 2, bd + k * 2, IDESC, (k == 0) ? acc : 1u);
                mma_tf32_ss(tmem + 256, ad1 + k * 2, bd + k * 2, IDESC, (k == 0) ? acc : 1u);
            }
            TC_COMMIT(bar);
        }
        // no trailing sync: next iteration's MBAR_WAIT provides the ordering
    }

    // drain last commit, then epilogue
    {
        const int last = NK - 1;
        MBAR_WAIT(sb + SM_BAR + 8 * (last % NSTAGE), (uint32_t)((last / NSTAGE) & 1));
    }
    TC_FENCE_AFTER();

    // D: rows 0-127 in cols [0,256), rows 128-255 in cols [256,512)
    const int half = wid >> 2;                    // 0 or 1
    const uint32_t dbase = tmem + half * 256;
    const size_t row = (size_t)(m_base + half * 128 + (wid & 3) * 32 + lid);
#pragma unroll
    for (int c0 = 0; c0 < NT; c0 += 32) {
        uint32_t r[32];
        TC_LD_32X32B_X32(r, dbase + c0);
        TC_WAIT_LD();
        float* dst = y + row * OUT_F + n_base + c0;
#pragma unroll
        for (int c = 0; c < 32; c += 4) {
            float4 o;
            o.x = __uint_as_float(r[c + 0]) + __ldg(bias + n_base + c0 + c + 0);
            o.y = __uint_as_float(r[c + 1]) + __ldg(bias + n_base + c0 + c + 1);
            o.z = __uint_as_float(r[c + 2]) + __ldg(bias + n_base + c0 + c + 2);
            o.w = __uint_as_float(r[c + 3]) + __ldg(bias + n_base + c0 + c + 3);
            *(float4*)(dst + c) = o;
        }
    }
    TC_FENCE_BEFORE();
    __syncthreads();
    if (wid == 0) TC_DEALLOC(tmem, 512);

#else  // ---------------- non-sm_103a fallback (plain sm_103 pass) -----------
    float* wsm = (float*)smem;              // [32][33]
    for (int mb = 0; mb < MT; mb += NTHREADS) {
        const int m = m_base + mb + tid;
        const float* xrow = x + (size_t)m * IN_F;
        for (int nb = 0; nb < NT; nb += 32) {
            float acc[32];
#pragma unroll
            for (int j = 0; j < 32; ++j) acc[j] = 0.0f;
            for (int k0 = 0; k0 < k_total; k0 += 32) {
                for (int e = tid; e < 32 * 32; e += NTHREADS) {
                    int j = e >> 5, kk = e & 31;
                    wsm[j * 33 + kk] = g_W[(size_t)(n_base + nb + j) * IN_F + k0 + kk];
                }
                __syncthreads();
#pragma unroll 8
                for (int kk = 0; kk < 32; ++kk) {
                    float xv = __ldg(xrow + k0 + kk);
#pragma unroll
                    for (int j = 0; j < 32; ++j) acc[j] += xv * wsm[j * 33 + kk];
                }
                __syncthreads();
            }
            float* dst = y + (size_t)m * OUT_F + n_base + nb;
#pragma unroll
            for (int j = 0; j < 32; ++j) dst[j] = acc[j] + __ldg(bias + n_base + nb + j);
        }
    }
#endif
}

// ---------------- launch ----------------
extern "C" void kernel_launch(void* const* d_in, const int* in_sizes, int n_in,
                              void* d_out, int out_size) {
    const float* x    = (const float*)d_in[0];
    const float* vals = (const float*)d_in[1];
    const float* bias = (const float*)d_in[2];
    const int*   rows = (const int*)d_in[3];
    const int*   cols = (const int*)d_in[4];
    float* y = (float*)d_out;

    const int nnz     = in_sizes[1];
    const int n_nodes = in_sizes[0] / IN_F;

    zero_w_kernel<<<1024, 1024>>>();
    scatter_kernel<<<(nnz + 255) / 256, 256>>>(vals, rows, cols, nnz);

    cudaFuncSetAttribute(gemm_tf32_kernel,
                         cudaFuncAttributeMaxDynamicSharedMemorySize, SMEM_TOTAL);
    dim3 grid(OUT_F / NT, n_nodes / MT);   // (8, 256), n fastest
    gemm_tf32_kernel<<<grid, NTHREADS, SMEM_TOTAL>>>(x, bias, y, IN_F);
}